// round 1
// baseline (speedup 1.0000x reference)
#include <cuda_runtime.h>
#include <math.h>

#define SQ 512     // sequence length S
#define HD 512     // hidden H
#define NB 256     // H/2

// Scratch for the two precomputed projections a = f@W1[:H], c = f@W1[H:]
__device__ float g_a[1024 * 512];
__device__ float g_c[1024 * 512];

// ---------- packed fp32x2 helpers (sm_103a FFMA2 path) ----------
__device__ __forceinline__ unsigned long long pack2(float lo, float hi) {
    unsigned long long r;
    asm("mov.b64 %0, {%1, %2};" : "=l"(r) : "f"(lo), "f"(hi));
    return r;
}
__device__ __forceinline__ void unpack2(unsigned long long v, float& lo, float& hi) {
    asm("mov.b64 {%0, %1}, %2;" : "=f"(lo), "=f"(hi) : "l"(v));
}
__device__ __forceinline__ void fma2(unsigned long long& d,
                                     unsigned long long a,
                                     unsigned long long b) {
    asm("fma.rn.f32x2 %0, %1, %2, %0;" : "+l"(d) : "l"(a), "l"(b));
}

// =====================================================================
// Kernel A: a[m,k] = sum_h f[m,h] * W1[h + z*512, k]   (z=0 -> a, z=1 -> c)
// Tiny (1 GFLOP) -- simple 64x64 smem-tiled GEMM.
// =====================================================================
__global__ __launch_bounds__(256) void gemm_ac_kernel(const float* __restrict__ f,
                                                      const float* __restrict__ W1) {
    const float* W = W1 + (size_t)blockIdx.z * HD * HD;
    float* out = blockIdx.z ? g_c : g_a;
    const int m0 = blockIdx.y * 64;
    const int n0 = blockIdx.x * 64;

    __shared__ float fT[16][65];   // [hh][m], padded
    __shared__ float ws[16][64];   // [hh][n]

    const int tid = threadIdx.x;
    const int tx = tid & 15, ty = tid >> 4;

    float acc[4][4];
#pragma unroll
    for (int r = 0; r < 4; r++)
#pragma unroll
        for (int c = 0; c < 4; c++) acc[r][c] = 0.f;

    for (int k0 = 0; k0 < HD; k0 += 16) {
        __syncthreads();
#pragma unroll
        for (int u = 0; u < 4; u++) {
            int e = u * 256 + tid;
            int m = e >> 4, hh = e & 15;
            fT[hh][m] = f[(size_t)(m0 + m) * HD + k0 + hh];
        }
#pragma unroll
        for (int u = 0; u < 4; u++) {
            int e = u * 256 + tid;
            int hh = e >> 6, n = e & 63;
            ws[hh][n] = W[(size_t)(k0 + hh) * HD + n0 + n];
        }
        __syncthreads();
#pragma unroll
        for (int hh = 0; hh < 16; hh++) {
            float fv[4];
#pragma unroll
            for (int r = 0; r < 4; r++) fv[r] = fT[hh][ty * 4 + r];
            float4 wv = *(const float4*)&ws[hh][tx * 4];
#pragma unroll
            for (int r = 0; r < 4; r++) {
                acc[r][0] += fv[r] * wv.x;
                acc[r][1] += fv[r] * wv.y;
                acc[r][2] += fv[r] * wv.z;
                acc[r][3] += fv[r] * wv.w;
            }
        }
    }
#pragma unroll
    for (int r = 0; r < 4; r++) {
        float4 o = make_float4(acc[r][0], acc[r][1], acc[r][2], acc[r][3]);
        *(float4*)&out[(size_t)(m0 + ty * 4 + r) * HD + n0 + tx * 4] = o;
    }
}

// =====================================================================
// Kernel B: fused pair MLP.
// CTA = 128 pairs (8 i x 16 j) x all 256 N.  K=512 streamed in 16-chunks.
// h1 chunk built on the fly into smem (relu(a_i + c_j + b1)), W2 chunk via
// cp.async, both double-buffered. Inner product in packed f32x2 FFMA2.
// Epilogue: +b2, relu, dot W3, half-warp shuffle reduce, sigmoid, store.
// =====================================================================
__global__ __launch_bounds__(256, 1) void pair_mlp_kernel(
    const float* __restrict__ b1, const float* __restrict__ W2,
    const float* __restrict__ b2, const float* __restrict__ W3,
    const float* __restrict__ b3, float* __restrict__ out) {

    __shared__ __align__(16) float h1s[2][16 * 128];  // [buf][kk*128 + p]
    __shared__ __align__(16) float w2s[2][16 * 256];  // [buf][kk*256 + n]

    const int tid = threadIdx.x;
    const int tx = tid & 15, ty = tid >> 4;
    const int b = blockIdx.z;
    const int i0 = blockIdx.y * 8;
    const int j0 = blockIdx.x * 16;

    // mapping for the h1-build phase: thread owns pair ph, two k-lanes
    const int ph = tid & 127;
    const int ih = i0 + (ph >> 4);
    const int jh = j0 + (ph & 15);
    const float* arow = g_a + ((size_t)b * SQ + ih) * HD;
    const float* crow = g_c + ((size_t)b * SQ + jh) * HD;
    const int klbase = tid >> 7;  // 0 or 1

    unsigned long long acc[8][8];
#pragma unroll
    for (int mm = 0; mm < 8; mm++)
#pragma unroll
        for (int q = 0; q < 8; q++) acc[mm][q] = 0ULL;  // bits of (0.f,0.f)

    auto prefetch = [&](int t, int buf) {
        const int k0 = t * 16;
        // h1 chunk: 2048 elems, conflict-free STS (consecutive p per lane)
#pragma unroll
        for (int u = 0; u < 8; u++) {
            int kl = klbase + 2 * u;
            float v = arow[k0 + kl] + crow[k0 + kl] + __ldg(&b1[k0 + kl]);
            h1s[buf][kl * 128 + ph] = fmaxf(v, 0.f);
        }
        // W2 chunk [16 x 256] via cp.async (16B each, fully coalesced)
#pragma unroll
        for (int u = 0; u < 4; u++) {
            int fq = u * 256 + tid;
            const float* gp = W2 + (size_t)(k0 + (fq >> 6)) * NB + ((fq & 63) << 2);
            unsigned sa = (unsigned)__cvta_generic_to_shared(&w2s[buf][fq << 2]);
            asm volatile("cp.async.cg.shared.global [%0], [%1], 16;"
                         :: "r"(sa), "l"(gp) : "memory");
        }
        asm volatile("cp.async.commit_group;" ::: "memory");
    };

    prefetch(0, 0);

    for (int t = 0; t < 32; t++) {
        const int cur = t & 1;
        asm volatile("cp.async.wait_group 0;" ::: "memory");
        __syncthreads();
        if (t + 1 < 32) prefetch(t + 1, cur ^ 1);

        const float* hbase = &h1s[cur][ty * 8];
        const float* wbase = &w2s[cur][2 * tx];
#pragma unroll
        for (int kk = 0; kk < 16; kk++) {
            float4 ha = *(const float4*)(hbase + kk * 128);
            float4 hb = *(const float4*)(hbase + kk * 128 + 4);
            unsigned long long hp[8];
            hp[0] = pack2(ha.x, ha.x); hp[1] = pack2(ha.y, ha.y);
            hp[2] = pack2(ha.z, ha.z); hp[3] = pack2(ha.w, ha.w);
            hp[4] = pack2(hb.x, hb.x); hp[5] = pack2(hb.y, hb.y);
            hp[6] = pack2(hb.z, hb.z); hp[7] = pack2(hb.w, hb.w);
            unsigned long long wq[8];
#pragma unroll
            for (int q = 0; q < 8; q++)
                wq[q] = *(const unsigned long long*)(wbase + kk * 256 + q * 32);
#pragma unroll
            for (int mm = 0; mm < 8; mm++)
#pragma unroll
                for (int q = 0; q < 8; q++) fma2(acc[mm][q], hp[mm], wq[q]);
        }
    }

    // Epilogue: h2 = relu(acc + b2); logit = h2 . W3 + b3; sigmoid.
    const float b3v = __ldg(b3);
#pragma unroll
    for (int mm = 0; mm < 8; mm++) {
        float partial = 0.f;
#pragma unroll
        for (int q = 0; q < 8; q++) {
            float lo, hi;
            unpack2(acc[mm][q], lo, hi);
            const int n0 = q * 32 + 2 * tx;   // pair covers (n0, n0+1)
            float2 bb = __ldg((const float2*)&b2[n0]);
            float2 ww = __ldg((const float2*)&W3[n0]);
            partial += fmaxf(lo + bb.x, 0.f) * ww.x +
                       fmaxf(hi + bb.y, 0.f) * ww.y;
        }
        // reduce across the 16 tx lanes (two independent 16-lane groups / warp)
#pragma unroll
        for (int s = 8; s > 0; s >>= 1)
            partial += __shfl_down_sync(0xffffffffu, partial, s);
        if (tx == 0) {
            const int p = ty * 8 + mm;
            const int i = i0 + (p >> 4);
            const int j = j0 + (p & 15);
            const float lg = partial + b3v;
            out[((size_t)b * SQ + i) * SQ + j] = 1.f / (1.f + expf(-lg));
        }
    }
}

extern "C" void kernel_launch(void* const* d_in, const int* in_sizes, int n_in,
                              void* d_out, int out_size) {
    const float* f  = (const float*)d_in[0];
    const float* W1 = (const float*)d_in[1];
    const float* b1 = (const float*)d_in[2];
    const float* W2 = (const float*)d_in[3];
    const float* b2 = (const float*)d_in[4];
    const float* W3 = (const float*)d_in[5];
    const float* b3 = (const float*)d_in[6];
    float* out = (float*)d_out;

    // a/c projections: grid (Ncols/64=8, Mrows/64=16, 2)
    gemm_ac_kernel<<<dim3(8, 16, 2), 256>>>(f, W1);
    // pair MLP: grid (S/16 j-tiles, S/8 i-tiles, B)
    pair_mlp_kernel<<<dim3(32, 64, 2), 256>>>(b1, W2, b2, W3, b3, out);
}

// round 3
// speedup vs baseline: 2.4570x; 2.4570x over previous
#include <cuda_runtime.h>
#include <cuda_bf16.h>
#include <cstdint>
#include <math.h>

#define SQ 512
#define HD 512
#define NB 256

// ---------------- device scratch ----------------
__device__ float g_a[1024 * 512];
__device__ float g_c[1024 * 512];
__device__ __nv_bfloat16 g_w2t_hi[NB * HD];   // W2^T hi [n][k]
__device__ __nv_bfloat16 g_w2t_lo[NB * HD];   // W2^T lo [n][k]

// ---------------- smem layout (bytes) ----------------
static constexpr int SM_A   = 0;        // [buf][hl][128 rows][128B]  2*2*16384
static constexpr int SM_B   = 65536;    // [buf][hl][256 rows][128B]  2*2*32768
static constexpr int SM_ACS = 196608;   // [buf][24 rows][272B]       2*6528
static constexpr int SM_B1  = 209664;   // 2048
static constexpr int SM_B2  = 211712;   // 1024
static constexpr int SM_W3  = 212736;   // 1024
static constexpr int SM_PSM = 213760;   // 128*2 floats
static constexpr int SMEM_TOTAL = 214784;

__device__ __forceinline__ uint32_t smem_u32(const void* p) {
    uint32_t a;
    asm("{ .reg .u64 t; cvta.to.shared.u64 t, %1; cvt.u32.u64 %0, t; }" : "=r"(a) : "l"(p));
    return a;
}
__device__ __forceinline__ uint32_t sw128(uint32_t off) { return off ^ ((off >> 3) & 0x70); }
__device__ __forceinline__ uint32_t cvt_bf16x2(float hi, float lo) {
    uint32_t r;
    asm("cvt.rn.bf16x2.f32 %0, %1, %2;" : "=r"(r) : "f"(hi), "f"(lo));
    return r;
}

#define LDSM4(r, a) \
    asm volatile("ldmatrix.sync.aligned.m8n8.x4.shared.b16 {%0,%1,%2,%3}, [%4];" \
        : "=r"((r)[0]), "=r"((r)[1]), "=r"((r)[2]), "=r"((r)[3]) : "r"(a))

#define MMA16816(c, a, b0v, b1v) \
    asm volatile("mma.sync.aligned.m16n8k16.row.col.f32.bf16.bf16.f32 " \
        "{%0,%1,%2,%3}, {%4,%5,%6,%7}, {%8,%9}, {%0,%1,%2,%3};" \
        : "+f"((c)[0]), "+f"((c)[1]), "+f"((c)[2]), "+f"((c)[3]) \
        : "r"((a)[0]), "r"((a)[1]), "r"((a)[2]), "r"((a)[3]), "r"(b0v), "r"(b1v))

#define CP16(dst, src) \
    asm volatile("cp.async.cg.shared.global [%0], [%1], 16;" :: "r"(dst), "l"(src) : "memory")

// =====================================================================
// Kernel A: a/c projections (known good)
// =====================================================================
__global__ __launch_bounds__(256) void gemm_ac_kernel(const float* __restrict__ f,
                                                      const float* __restrict__ W1) {
    const float* W = W1 + (size_t)blockIdx.z * HD * HD;
    float* out = blockIdx.z ? g_c : g_a;
    const int m0 = blockIdx.y * 64;
    const int n0 = blockIdx.x * 64;

    __shared__ float fT[16][65];
    __shared__ float ws[16][64];

    const int tid = threadIdx.x;
    const int tx = tid & 15, ty = tid >> 4;

    float acc[4][4];
#pragma unroll
    for (int r = 0; r < 4; r++)
#pragma unroll
        for (int c = 0; c < 4; c++) acc[r][c] = 0.f;

    for (int k0 = 0; k0 < HD; k0 += 16) {
        __syncthreads();
#pragma unroll
        for (int u = 0; u < 4; u++) {
            int e = u * 256 + tid;
            int m = e >> 4, hh = e & 15;
            fT[hh][m] = f[(size_t)(m0 + m) * HD + k0 + hh];
        }
#pragma unroll
        for (int u = 0; u < 4; u++) {
            int e = u * 256 + tid;
            int hh = e >> 6, n = e & 63;
            ws[hh][n] = W[(size_t)(k0 + hh) * HD + n0 + n];
        }
        __syncthreads();
#pragma unroll
        for (int hh = 0; hh < 16; hh++) {
            float fv[4];
#pragma unroll
            for (int r = 0; r < 4; r++) fv[r] = fT[hh][ty * 4 + r];
            float4 wv = *(const float4*)&ws[hh][tx * 4];
#pragma unroll
            for (int r = 0; r < 4; r++) {
                acc[r][0] += fv[r] * wv.x;
                acc[r][1] += fv[r] * wv.y;
                acc[r][2] += fv[r] * wv.z;
                acc[r][3] += fv[r] * wv.w;
            }
        }
    }
#pragma unroll
    for (int r = 0; r < 4; r++) {
        float4 o = make_float4(acc[r][0], acc[r][1], acc[r][2], acc[r][3]);
        *(float4*)&out[(size_t)(m0 + ty * 4 + r) * HD + n0 + tx * 4] = o;
    }
}

// =====================================================================
// Kernel B: split W2 -> bf16 hi/lo transposed [n][k]
// =====================================================================
__global__ void w2prep_kernel(const float* __restrict__ W2) {
    int idx = blockIdx.x * 256 + threadIdx.x;
    int k = idx >> 8, n = idx & 255;
    float w = W2[idx];
    __nv_bfloat16 h = __float2bfloat16(w);
    float rem = w - __bfloat162float(h);
    g_w2t_hi[n * HD + k] = h;
    g_w2t_lo[n * HD + k] = __float2bfloat16(rem);
}

// =====================================================================
// Kernel C: fused pair MLP on HMMA (mma.sync, 3-pass bf16 split)
// CTA: 128 pairs (8i x 16j) x N=256, K=512 in 8 chunks of 64.
// =====================================================================
__device__ __forceinline__ void prefetch_chunk(char* smem, int t, int buf, int tid,
                                               int bz, int i0, int j0) {
    // B chunk: hi/lo, 256 rows x 128B each, SW128
#pragma unroll
    for (int h = 0; h < 2; ++h) {
        const __nv_bfloat16* src = h ? g_w2t_lo : g_w2t_hi;
        char* base = smem + SM_B + buf * 65536 + h * 32768;
#pragma unroll
        for (int u = 0; u < 8; ++u) {
            int s = u * 256 + tid;
            int n = s >> 3, g = s & 7;
            uint32_t dst = smem_u32(base) + sw128((uint32_t)(n * 128 + g * 16));
            CP16(dst, src + (size_t)n * HD + t * 64 + g * 8);
        }
    }
    // acs chunk: 8 a-rows + 16 c-rows, 64 floats each (row pitch 272B)
    char* acb = smem + SM_ACS + buf * 6528;
#pragma unroll
    for (int u = 0; u < 2; ++u) {
        int s = u * 256 + tid;
        if (s < 384) {
            int row = s >> 4, g = s & 15;
            const float* src = (row < 8)
                ? g_a + ((size_t)(bz * SQ + i0 + row)) * HD + t * 64 + g * 4
                : g_c + ((size_t)(bz * SQ + j0 + (row - 8))) * HD + t * 64 + g * 4;
            uint32_t dst = smem_u32(acb) + (uint32_t)(row * 272 + g * 16);
            CP16(dst, src);
        }
    }
    asm volatile("cp.async.commit_group;" ::: "memory");
}

__global__ __launch_bounds__(256, 1) void pair_hmma_kernel(
    const float* __restrict__ b1, const float* __restrict__ b2,
    const float* __restrict__ W3, const float* __restrict__ b3,
    float* __restrict__ out) {

    extern __shared__ char smem[];
    const int tid = threadIdx.x;
    const int wid = tid >> 5, lid = tid & 31;
    const int wm = wid >> 1, wn = wid & 1;
    const int bz = blockIdx.z;
    const int i0 = blockIdx.y * 8;
    const int j0 = blockIdx.x * 16;
    const uint32_t smb = smem_u32(smem);

    float* b1s = (float*)(smem + SM_B1);
    float* b2s = (float*)(smem + SM_B2);
    float* w3s = (float*)(smem + SM_W3);
    float* psm = (float*)(smem + SM_PSM);

    // stage biases
    if (tid < 128) ((float4*)b1s)[tid] = ((const float4*)b1)[tid];
    else if (tid < 192) ((float4*)b2s)[tid - 128] = ((const float4*)b2)[tid - 128];
    else ((float4*)w3s)[tid - 192] = ((const float4*)W3)[tid - 192];

    prefetch_chunk((char*)smem, 0, 0, tid, bz, i0, j0);

    float acc[2][16][4];
#pragma unroll
    for (int mf = 0; mf < 2; mf++)
#pragma unroll
        for (int nf = 0; nf < 16; nf++)
#pragma unroll
            for (int e = 0; e < 4; e++) acc[mf][nf][e] = 0.f;

    // ldmatrix per-lane constants
    const int rA = wm * 32 + (lid & 15);
    const uint32_t xorA = (uint32_t)((rA & 7) << 4);
    const int rB = wn * 128 + (lid & 15);
    const uint32_t xorB = (uint32_t)((rB & 7) << 4);
    const uint32_t khb = (uint32_t)((lid >> 4) << 4);

    // build-phase mapping: thread owns pair p, k-half kh (32 k values)
    const int p = tid & 127, kh = tid >> 7;
    const int iloc = p >> 4, jloc = p & 15;
    const uint32_t aXor = (uint32_t)((p & 7) << 4);

    for (int t = 0; t < 8; ++t) {
        const int cur = t & 1;
        asm volatile("cp.async.wait_group 0;" ::: "memory");
        __syncthreads();   // copies visible; prev-iter mma done -> bufs free

        if (t + 1 < 8) prefetch_chunk((char*)smem, t + 1, cur ^ 1, tid, bz, i0, j0);

        // ---- build A(t): h1 = relu(a_i + c_j + b1), split bf16 hi/lo ----
        {
            const float* arow = (const float*)(smem + SM_ACS + cur * 6528 + iloc * 272);
            const float* crow = (const float*)(smem + SM_ACS + cur * 6528 + (8 + jloc) * 272);
            uint32_t hi[16], lo[16];
#pragma unroll
            for (int q = 0; q < 8; ++q) {
                float4 av = *(const float4*)(arow + kh * 32 + q * 4);
                float4 cv = *(const float4*)(crow + kh * 32 + q * 4);
                float4 bb = *(const float4*)(b1s + t * 64 + kh * 32 + q * 4);
                float v0 = fmaxf(av.x + cv.x + bb.x, 0.f);
                float v1 = fmaxf(av.y + cv.y + bb.y, 0.f);
                float v2 = fmaxf(av.z + cv.z + bb.z, 0.f);
                float v3 = fmaxf(av.w + cv.w + bb.w, 0.f);
                uint32_t h01 = cvt_bf16x2(v1, v0);
                uint32_t h23 = cvt_bf16x2(v3, v2);
                float r0 = v0 - __uint_as_float(h01 << 16);
                float r1 = v1 - __uint_as_float(h01 & 0xffff0000u);
                float r2 = v2 - __uint_as_float(h23 << 16);
                float r3 = v3 - __uint_as_float(h23 & 0xffff0000u);
                hi[q * 2] = h01; hi[q * 2 + 1] = h23;
                lo[q * 2] = cvt_bf16x2(r1, r0); lo[q * 2 + 1] = cvt_bf16x2(r3, r2);
            }
            char* ah = (char*)smem + SM_A + cur * 32768;
            char* al = ah + 16384;
#pragma unroll
            for (int s = 0; s < 4; ++s) {
                uint32_t off = (uint32_t)(p * 128) + (((uint32_t)(kh * 64 + s * 16)) ^ aXor);
                *(uint4*)(ah + off) = make_uint4(hi[s*4], hi[s*4+1], hi[s*4+2], hi[s*4+3]);
                *(uint4*)(al + off) = make_uint4(lo[s*4], lo[s*4+1], lo[s*4+2], lo[s*4+3]);
            }
        }
        __syncthreads();   // A(t) visible

        // ---- mma over chunk t ----
        const uint32_t Ah = smb + SM_A + cur * 32768;
        const uint32_t Al = Ah + 16384;
        const uint32_t Bh = smb + SM_B + cur * 65536;
        const uint32_t Bl = Bh + 32768;
#pragma unroll
        for (int ks = 0; ks < 4; ++ks) {
            const uint32_t koff = ((uint32_t)(ks * 32) + khb);
            const uint32_t aoff = (uint32_t)(rA * 128) + (koff ^ xorA);
            uint32_t ah0[4], ah1[4], al0[4], al1[4];
            LDSM4(ah0, Ah + aoff);
            LDSM4(ah1, Ah + aoff + 16 * 128);
            LDSM4(al0, Al + aoff);
            LDSM4(al1, Al + aoff + 16 * 128);
            const uint32_t bko = koff ^ xorB;
#pragma unroll
            for (int nfp = 0; nfp < 8; ++nfp) {
                uint32_t boff = (uint32_t)((rB + nfp * 16) * 128) + bko;
                uint32_t bh[4], bl[4];
                LDSM4(bh, Bh + boff);
                LDSM4(bl, Bl + boff);
                // nf0 = 2*nfp: b = {r0, r2}; nf1 = 2*nfp+1: b = {r1, r3}
                MMA16816(acc[0][2 * nfp],     ah0, bh[0], bh[2]);
                MMA16816(acc[0][2 * nfp],     ah0, bl[0], bl[2]);
                MMA16816(acc[0][2 * nfp],     al0, bh[0], bh[2]);
                MMA16816(acc[0][2 * nfp + 1], ah0, bh[1], bh[3]);
                MMA16816(acc[0][2 * nfp + 1], ah0, bl[1], bl[3]);
                MMA16816(acc[0][2 * nfp + 1], al0, bh[1], bh[3]);
                MMA16816(acc[1][2 * nfp],     ah1, bh[0], bh[2]);
                MMA16816(acc[1][2 * nfp],     ah1, bl[0], bl[2]);
                MMA16816(acc[1][2 * nfp],     al1, bh[0], bh[2]);
                MMA16816(acc[1][2 * nfp + 1], ah1, bh[1], bh[3]);
                MMA16816(acc[1][2 * nfp + 1], ah1, bl[1], bl[3]);
                MMA16816(acc[1][2 * nfp + 1], al1, bh[1], bh[3]);
            }
        }
    }

    // ---- epilogue: relu(+b2) . W3, reduce, sigmoid ----
    float pr[2][2] = {{0.f, 0.f}, {0.f, 0.f}};
#pragma unroll
    for (int nf = 0; nf < 16; ++nf) {
        const int n = wn * 128 + nf * 8 + 2 * (lid & 3);
        const float b2x = b2s[n], b2y = b2s[n + 1];
        const float w3x = w3s[n], w3y = w3s[n + 1];
#pragma unroll
        for (int mf = 0; mf < 2; ++mf) {
            pr[mf][0] += fmaxf(acc[mf][nf][0] + b2x, 0.f) * w3x
                       + fmaxf(acc[mf][nf][1] + b2y, 0.f) * w3y;
            pr[mf][1] += fmaxf(acc[mf][nf][2] + b2x, 0.f) * w3x
                       + fmaxf(acc[mf][nf][3] + b2y, 0.f) * w3y;
        }
    }
#pragma unroll
    for (int mf = 0; mf < 2; ++mf)
#pragma unroll
        for (int h = 0; h < 2; ++h) {
            pr[mf][h] += __shfl_xor_sync(0xffffffffu, pr[mf][h], 1);
            pr[mf][h] += __shfl_xor_sync(0xffffffffu, pr[mf][h], 2);
        }
    if ((lid & 3) == 0) {
#pragma unroll
        for (int mf = 0; mf < 2; ++mf)
#pragma unroll
            for (int h = 0; h < 2; ++h) {
                int row = wm * 32 + mf * 16 + (lid >> 2) + h * 8;
                psm[row * 2 + wn] = pr[mf][h];
            }
    }
    __syncthreads();
    if (tid < 128) {
        const float b3v = __ldg(b3);
        float lg = psm[tid * 2] + psm[tid * 2 + 1] + b3v;
        const int i = i0 + (tid >> 4);
        const int j = j0 + (tid & 15);
        out[((size_t)bz * SQ + i) * SQ + j] = 1.f / (1.f + __expf(-lg));
    }
}

// =====================================================================
extern "C" void kernel_launch(void* const* d_in, const int* in_sizes, int n_in,
                              void* d_out, int out_size) {
    const float* f  = (const float*)d_in[0];
    const float* W1 = (const float*)d_in[1];
    const float* b1 = (const float*)d_in[2];
    const float* W2 = (const float*)d_in[3];
    const float* b2 = (const float*)d_in[4];
    const float* W3 = (const float*)d_in[5];
    const float* b3 = (const float*)d_in[6];
    float* out = (float*)d_out;

    cudaFuncSetAttribute(pair_hmma_kernel,
                         cudaFuncAttributeMaxDynamicSharedMemorySize, SMEM_TOTAL);

    gemm_ac_kernel<<<dim3(8, 16, 2), 256>>>(f, W1);
    w2prep_kernel<<<512, 256>>>(W2);
    pair_hmma_kernel<<<dim3(32, 64, 2), 256, SMEM_TOTAL>>>(b1, b2, W3, b3, out);
}

// round 4
// speedup vs baseline: 3.5233x; 1.4340x over previous
#include <cuda_runtime.h>
#include <cuda_fp16.h>
#include <cstdint>
#include <math.h>

#define SQ 512
#define HD 512
#define NB 256

// ---------------- device scratch ----------------
__device__ float g_a[1024 * 512];
__device__ float g_c[1024 * 512];
__device__ __half g_w2t_hi[NB * HD];   // W2^T hi [n][k] fp16
__device__ __half g_w2t_lo[NB * HD];   // W2^T lo [n][k] fp16

// ---------------- smem layout (bytes) ----------------
static constexpr int SM_A   = 0;        // [buf][128 rows][128B]       2*16384
static constexpr int SM_B   = 32768;    // [buf][hl][256 rows][128B]   2*2*32768
static constexpr int SM_ACS = 163840;   // [buf][24 rows][272B]        2*6528
static constexpr int SM_B1  = 176896;   // 2048
static constexpr int SM_B2  = 178944;   // 1024
static constexpr int SM_W3  = 179968;   // 1024
static constexpr int SM_PSM = 180992;   // 128*2 floats
static constexpr int SMEM_TOTAL = 182016;

__device__ __forceinline__ uint32_t smem_u32(const void* p) {
    uint32_t a;
    asm("{ .reg .u64 t; cvta.to.shared.u64 t, %1; cvt.u32.u64 %0, t; }" : "=r"(a) : "l"(p));
    return a;
}
__device__ __forceinline__ uint32_t sw128(uint32_t off) { return off ^ ((off >> 3) & 0x70); }
__device__ __forceinline__ uint32_t cvt_f16x2(float lo, float hi) {
    // returns packed fp16x2 with 'lo' in low 16 bits
    __half2 h = __floats2half2_rn(lo, hi);
    return *(uint32_t*)&h;
}

#define LDSM4(r, a) \
    asm volatile("ldmatrix.sync.aligned.m8n8.x4.shared.b16 {%0,%1,%2,%3}, [%4];" \
        : "=r"((r)[0]), "=r"((r)[1]), "=r"((r)[2]), "=r"((r)[3]) : "r"(a))

#define MMA16816(c, a, b0v, b1v) \
    asm volatile("mma.sync.aligned.m16n8k16.row.col.f32.f16.f16.f32 " \
        "{%0,%1,%2,%3}, {%4,%5,%6,%7}, {%8,%9}, {%0,%1,%2,%3};" \
        : "+f"((c)[0]), "+f"((c)[1]), "+f"((c)[2]), "+f"((c)[3]) \
        : "r"((a)[0]), "r"((a)[1]), "r"((a)[2]), "r"((a)[3]), "r"(b0v), "r"(b1v))

#define CP16(dst, src) \
    asm volatile("cp.async.cg.shared.global [%0], [%1], 16;" :: "r"(dst), "l"(src) : "memory")

// =====================================================================
// Kernel A: a/c projections
// =====================================================================
__global__ __launch_bounds__(256) void gemm_ac_kernel(const float* __restrict__ f,
                                                      const float* __restrict__ W1) {
    const float* W = W1 + (size_t)blockIdx.z * HD * HD;
    float* out = blockIdx.z ? g_c : g_a;
    const int m0 = blockIdx.y * 64;
    const int n0 = blockIdx.x * 64;

    __shared__ float fT[16][65];
    __shared__ float ws[16][64];

    const int tid = threadIdx.x;
    const int tx = tid & 15, ty = tid >> 4;

    float acc[4][4];
#pragma unroll
    for (int r = 0; r < 4; r++)
#pragma unroll
        for (int c = 0; c < 4; c++) acc[r][c] = 0.f;

    for (int k0 = 0; k0 < HD; k0 += 16) {
        __syncthreads();
#pragma unroll
        for (int u = 0; u < 4; u++) {
            int e = u * 256 + tid;
            int m = e >> 4, hh = e & 15;
            fT[hh][m] = f[(size_t)(m0 + m) * HD + k0 + hh];
        }
#pragma unroll
        for (int u = 0; u < 4; u++) {
            int e = u * 256 + tid;
            int hh = e >> 6, n = e & 63;
            ws[hh][n] = W[(size_t)(k0 + hh) * HD + n0 + n];
        }
        __syncthreads();
#pragma unroll
        for (int hh = 0; hh < 16; hh++) {
            float fv[4];
#pragma unroll
            for (int r = 0; r < 4; r++) fv[r] = fT[hh][ty * 4 + r];
            float4 wv = *(const float4*)&ws[hh][tx * 4];
#pragma unroll
            for (int r = 0; r < 4; r++) {
                acc[r][0] += fv[r] * wv.x;
                acc[r][1] += fv[r] * wv.y;
                acc[r][2] += fv[r] * wv.z;
                acc[r][3] += fv[r] * wv.w;
            }
        }
    }
#pragma unroll
    for (int r = 0; r < 4; r++) {
        float4 o = make_float4(acc[r][0], acc[r][1], acc[r][2], acc[r][3]);
        *(float4*)&out[(size_t)(m0 + ty * 4 + r) * HD + n0 + tx * 4] = o;
    }
}

// =====================================================================
// Kernel B: split W2 -> fp16 hi/lo transposed [n][k]
// =====================================================================
__global__ void w2prep_kernel(const float* __restrict__ W2) {
    int idx = blockIdx.x * 256 + threadIdx.x;
    int k = idx >> 8, n = idx & 255;
    float w = W2[idx];
    __half h = __float2half_rn(w);
    float rem = w - __half2float(h);
    g_w2t_hi[n * HD + k] = h;
    g_w2t_lo[n * HD + k] = __float2half_rn(rem);
}

// =====================================================================
// Kernel C: fused pair MLP, fp16 HMMA, 2-pass (A single, B split hi/lo)
// CTA: 128 pairs (8i x 16j) x N=256, K=512 in 8 chunks of 64.
// =====================================================================
__device__ __forceinline__ void prefetch_chunk(char* smem, int t, int buf, int tid,
                                               int bz, int i0, int j0) {
    // B chunk: hi/lo, 256 rows x 128B each, SW128
#pragma unroll
    for (int h = 0; h < 2; ++h) {
        const __half* src = h ? g_w2t_lo : g_w2t_hi;
        char* base = smem + SM_B + buf * 65536 + h * 32768;
#pragma unroll
        for (int u = 0; u < 8; ++u) {
            int s = u * 256 + tid;
            int n = s >> 3, g = s & 7;
            uint32_t dst = smem_u32(base) + sw128((uint32_t)(n * 128 + g * 16));
            CP16(dst, src + (size_t)n * HD + t * 64 + g * 8);
        }
    }
    // acs chunk: 8 a-rows + 16 c-rows, 64 floats each (row pitch 272B)
    char* acb = smem + SM_ACS + buf * 6528;
#pragma unroll
    for (int u = 0; u < 2; ++u) {
        int s = u * 256 + tid;
        if (s < 384) {
            int row = s >> 4, g = s & 15;
            const float* src = (row < 8)
                ? g_a + ((size_t)(bz * SQ + i0 + row)) * HD + t * 64 + g * 4
                : g_c + ((size_t)(bz * SQ + j0 + (row - 8))) * HD + t * 64 + g * 4;
            uint32_t dst = smem_u32(acb) + (uint32_t)(row * 272 + g * 16);
            CP16(dst, src);
        }
    }
    asm volatile("cp.async.commit_group;" ::: "memory");
}

__global__ __launch_bounds__(256, 1) void pair_hmma_kernel(
    const float* __restrict__ b1, const float* __restrict__ b2,
    const float* __restrict__ W3, const float* __restrict__ b3,
    float* __restrict__ out) {

    extern __shared__ char smem[];
    const int tid = threadIdx.x;
    const int wid = tid >> 5, lid = tid & 31;
    const int wm = wid >> 1, wn = wid & 1;
    const int bz = blockIdx.z;
    const int i0 = blockIdx.y * 8;
    const int j0 = blockIdx.x * 16;
    const uint32_t smb = smem_u32(smem);

    float* b1s = (float*)(smem + SM_B1);
    float* b2s = (float*)(smem + SM_B2);
    float* w3s = (float*)(smem + SM_W3);
    float* psm = (float*)(smem + SM_PSM);

    // stage biases
    if (tid < 128) ((float4*)b1s)[tid] = ((const float4*)b1)[tid];
    else if (tid < 192) ((float4*)b2s)[tid - 128] = ((const float4*)b2)[tid - 128];
    else ((float4*)w3s)[tid - 192] = ((const float4*)W3)[tid - 192];

    prefetch_chunk((char*)smem, 0, 0, tid, bz, i0, j0);

    float acc[2][16][4];
#pragma unroll
    for (int mf = 0; mf < 2; mf++)
#pragma unroll
        for (int nf = 0; nf < 16; nf++)
#pragma unroll
            for (int e = 0; e < 4; e++) acc[mf][nf][e] = 0.f;

    // ldmatrix per-lane constants
    const int rA = wm * 32 + (lid & 15);
    const uint32_t xorA = (uint32_t)((rA & 7) << 4);
    const int rB = wn * 128 + (lid & 15);
    const uint32_t xorB = (uint32_t)((rB & 7) << 4);
    const uint32_t khb = (uint32_t)((lid >> 4) << 4);

    // build-phase mapping: thread owns pair p, k-half kh (32 k values)
    const int p = tid & 127, kh = tid >> 7;
    const int iloc = p >> 4, jloc = p & 15;
    const uint32_t aXor = (uint32_t)((p & 7) << 4);

    for (int t = 0; t < 8; ++t) {
        const int cur = t & 1;
        asm volatile("cp.async.wait_group 0;" ::: "memory");
        __syncthreads();   // chunk t data visible; prev MMA done -> bufs free

        if (t + 1 < 8) prefetch_chunk((char*)smem, t + 1, cur ^ 1, tid, bz, i0, j0);

        // ---- build A(t): h1 = relu(a_i + c_j + b1) -> single fp16 ----
        {
            const float* arow = (const float*)(smem + SM_ACS + cur * 6528 + iloc * 272);
            const float* crow = (const float*)(smem + SM_ACS + cur * 6528 + (8 + jloc) * 272);
            uint32_t hi[16];
#pragma unroll
            for (int q = 0; q < 8; ++q) {
                float4 av = *(const float4*)(arow + kh * 32 + q * 4);
                float4 cv = *(const float4*)(crow + kh * 32 + q * 4);
                float4 bb = *(const float4*)(b1s + t * 64 + kh * 32 + q * 4);
                float v0 = fmaxf(av.x + cv.x + bb.x, 0.f);
                float v1 = fmaxf(av.y + cv.y + bb.y, 0.f);
                float v2 = fmaxf(av.z + cv.z + bb.z, 0.f);
                float v3 = fmaxf(av.w + cv.w + bb.w, 0.f);
                hi[q * 2]     = cvt_f16x2(v0, v1);
                hi[q * 2 + 1] = cvt_f16x2(v2, v3);
            }
            char* ah = (char*)smem + SM_A + cur * 16384;
#pragma unroll
            for (int s = 0; s < 4; ++s) {
                uint32_t off = (uint32_t)(p * 128) + (((uint32_t)(kh * 64 + s * 16)) ^ aXor);
                *(uint4*)(ah + off) = make_uint4(hi[s*4], hi[s*4+1], hi[s*4+2], hi[s*4+3]);
            }
        }
        __syncthreads();   // A(t) visible

        // ---- mma over chunk t: Af*Bhi + Af*Blo ----
        const uint32_t Ah = smb + SM_A + cur * 16384;
        const uint32_t Bh = smb + SM_B + cur * 65536;
        const uint32_t Bl = Bh + 32768;
#pragma unroll
        for (int ks = 0; ks < 4; ++ks) {
            const uint32_t koff = ((uint32_t)(ks * 32) + khb);
            const uint32_t aoff = (uint32_t)(rA * 128) + (koff ^ xorA);
            uint32_t ah0[4], ah1[4];
            LDSM4(ah0, Ah + aoff);
            LDSM4(ah1, Ah + aoff + 16 * 128);
            const uint32_t bko = koff ^ xorB;
#pragma unroll
            for (int nfp = 0; nfp < 8; ++nfp) {
                uint32_t boff = (uint32_t)((rB + nfp * 16) * 128) + bko;
                uint32_t bh[4], bl[4];
                LDSM4(bh, Bh + boff);
                LDSM4(bl, Bl + boff);
                MMA16816(acc[0][2 * nfp],     ah0, bh[0], bh[2]);
                MMA16816(acc[0][2 * nfp],     ah0, bl[0], bl[2]);
                MMA16816(acc[0][2 * nfp + 1], ah0, bh[1], bh[3]);
                MMA16816(acc[0][2 * nfp + 1], ah0, bl[1], bl[3]);
                MMA16816(acc[1][2 * nfp],     ah1, bh[0], bh[2]);
                MMA16816(acc[1][2 * nfp],     ah1, bl[0], bl[2]);
                MMA16816(acc[1][2 * nfp + 1], ah1, bh[1], bh[3]);
                MMA16816(acc[1][2 * nfp + 1], ah1, bl[1], bl[3]);
            }
        }
    }

    // ---- epilogue: relu(+b2) . W3, reduce, sigmoid ----
    float pr[2][2] = {{0.f, 0.f}, {0.f, 0.f}};
#pragma unroll
    for (int nf = 0; nf < 16; ++nf) {
        const int n = wn * 128 + nf * 8 + 2 * (lid & 3);
        const float b2x = b2s[n], b2y = b2s[n + 1];
        const float w3x = w3s[n], w3y = w3s[n + 1];
#pragma unroll
        for (int mf = 0; mf < 2; ++mf) {
            pr[mf][0] += fmaxf(acc[mf][nf][0] + b2x, 0.f) * w3x
                       + fmaxf(acc[mf][nf][1] + b2y, 0.f) * w3y;
            pr[mf][1] += fmaxf(acc[mf][nf][2] + b2x, 0.f) * w3x
                       + fmaxf(acc[mf][nf][3] + b2y, 0.f) * w3y;
        }
    }
#pragma unroll
    for (int mf = 0; mf < 2; ++mf)
#pragma unroll
        for (int h = 0; h < 2; ++h) {
            pr[mf][h] += __shfl_xor_sync(0xffffffffu, pr[mf][h], 1);
            pr[mf][h] += __shfl_xor_sync(0xffffffffu, pr[mf][h], 2);
        }
    if ((lid & 3) == 0) {
#pragma unroll
        for (int mf = 0; mf < 2; ++mf)
#pragma unroll
            for (int h = 0; h < 2; ++h) {
                int row = wm * 32 + mf * 16 + (lid >> 2) + h * 8;
                psm[row * 2 + wn] = pr[mf][h];
            }
    }
    __syncthreads();
    if (tid < 128) {
        const float b3v = __ldg(b3);
        float lg = psm[tid * 2] + psm[tid * 2 + 1] + b3v;
        const int i = i0 + (tid >> 4);
        const int j = j0 + (tid & 15);
        out[((size_t)bz * SQ + i) * SQ + j] = 1.f / (1.f + __expf(-lg));
    }
}

// =====================================================================
extern "C" void kernel_launch(void* const* d_in, const int* in_sizes, int n_in,
                              void* d_out, int out_size) {
    const float* f  = (const float*)d_in[0];
    const float* W1 = (const float*)d_in[1];
    const float* b1 = (const float*)d_in[2];
    const float* W2 = (const float*)d_in[3];
    const float* b2 = (const float*)d_in[4];
    const float* W3 = (const float*)d_in[5];
    const float* b3 = (const float*)d_in[6];
    float* out = (float*)d_out;

    cudaFuncSetAttribute(pair_hmma_kernel,
                         cudaFuncAttributeMaxDynamicSharedMemorySize, SMEM_TOTAL);

    gemm_ac_kernel<<<dim3(8, 16, 2), 256>>>(f, W1);
    w2prep_kernel<<<512, 256>>>(W2);
    pair_hmma_kernel<<<dim3(32, 64, 2), 256, SMEM_TOTAL>>>(b1, b2, W3, b3, out);
}

// round 5
// speedup vs baseline: 5.5082x; 1.5633x over previous
#include <cuda_runtime.h>
#include <cuda_fp16.h>
#include <cstdint>
#include <math.h>

#define SQ 512
#define HD 512
#define NB 256

// ---------------- device scratch ----------------
__device__ float g_a[1024 * 512];
__device__ float g_c[1024 * 512];
__device__ __half g_w2t[NB * HD];   // W2^T fp16 [n][k]

// ---------------- smem layout (bytes) ----------------
static constexpr int SM_A   = 0;        // [buf][128 rows][128B]   2*16384
static constexpr int SM_B   = 32768;    // [buf][256 rows][128B]   2*32768
static constexpr int SM_ACS = 98304;    // [buf][24 rows][272B]    2*6528
static constexpr int SM_B1  = 111360;   // 2048
static constexpr int SM_B2  = 113408;   // 1024
static constexpr int SM_W3  = 114432;   // 1024
static constexpr int SM_PSM = 115456;   // 128*2 floats
static constexpr int SMEM_TOTAL = 116480;

__device__ __forceinline__ uint32_t smem_u32(const void* p) {
    uint32_t a;
    asm("{ .reg .u64 t; cvta.to.shared.u64 t, %1; cvt.u32.u64 %0, t; }" : "=r"(a) : "l"(p));
    return a;
}
__device__ __forceinline__ uint32_t sw128(uint32_t off) { return off ^ ((off >> 3) & 0x70); }
__device__ __forceinline__ uint32_t cvt_f16x2(float lo, float hi) {
    __half2 h = __floats2half2_rn(lo, hi);
    return *(uint32_t*)&h;
}

#define LDSM4(r, a) \
    asm volatile("ldmatrix.sync.aligned.m8n8.x4.shared.b16 {%0,%1,%2,%3}, [%4];" \
        : "=r"((r)[0]), "=r"((r)[1]), "=r"((r)[2]), "=r"((r)[3]) : "r"(a))

#define MMA16816(c, a, b0v, b1v) \
    asm volatile("mma.sync.aligned.m16n8k16.row.col.f32.f16.f16.f32 " \
        "{%0,%1,%2,%3}, {%4,%5,%6,%7}, {%8,%9}, {%0,%1,%2,%3};" \
        : "+f"((c)[0]), "+f"((c)[1]), "+f"((c)[2]), "+f"((c)[3]) \
        : "r"((a)[0]), "r"((a)[1]), "r"((a)[2]), "r"((a)[3]), "r"(b0v), "r"(b1v))

#define CP16(dst, src) \
    asm volatile("cp.async.cg.shared.global [%0], [%1], 16;" :: "r"(dst), "l"(src) : "memory")

// =====================================================================
// Kernel A: a/c projections
// =====================================================================
__global__ __launch_bounds__(256) void gemm_ac_kernel(const float* __restrict__ f,
                                                      const float* __restrict__ W1) {
    const float* W = W1 + (size_t)blockIdx.z * HD * HD;
    float* out = blockIdx.z ? g_c : g_a;
    const int m0 = blockIdx.y * 64;
    const int n0 = blockIdx.x * 64;

    __shared__ float fT[16][65];
    __shared__ float ws[16][64];

    const int tid = threadIdx.x;
    const int tx = tid & 15, ty = tid >> 4;

    float acc[4][4];
#pragma unroll
    for (int r = 0; r < 4; r++)
#pragma unroll
        for (int c = 0; c < 4; c++) acc[r][c] = 0.f;

    for (int k0 = 0; k0 < HD; k0 += 16) {
        __syncthreads();
#pragma unroll
        for (int u = 0; u < 4; u++) {
            int e = u * 256 + tid;
            int m = e >> 4, hh = e & 15;
            fT[hh][m] = f[(size_t)(m0 + m) * HD + k0 + hh];
        }
#pragma unroll
        for (int u = 0; u < 4; u++) {
            int e = u * 256 + tid;
            int hh = e >> 6, n = e & 63;
            ws[hh][n] = W[(size_t)(k0 + hh) * HD + n0 + n];
        }
        __syncthreads();
#pragma unroll
        for (int hh = 0; hh < 16; hh++) {
            float fv[4];
#pragma unroll
            for (int r = 0; r < 4; r++) fv[r] = fT[hh][ty * 4 + r];
            float4 wv = *(const float4*)&ws[hh][tx * 4];
#pragma unroll
            for (int r = 0; r < 4; r++) {
                acc[r][0] += fv[r] * wv.x;
                acc[r][1] += fv[r] * wv.y;
                acc[r][2] += fv[r] * wv.z;
                acc[r][3] += fv[r] * wv.w;
            }
        }
    }
#pragma unroll
    for (int r = 0; r < 4; r++) {
        float4 o = make_float4(acc[r][0], acc[r][1], acc[r][2], acc[r][3]);
        *(float4*)&out[(size_t)(m0 + ty * 4 + r) * HD + n0 + tx * 4] = o;
    }
}

// =====================================================================
// Kernel B: W2 -> fp16 transposed [n][k]
// =====================================================================
__global__ void w2prep_kernel(const float* __restrict__ W2) {
    int idx = blockIdx.x * 256 + threadIdx.x;
    int k = idx >> 8, n = idx & 255;
    g_w2t[n * HD + k] = __float2half_rn(W2[idx]);
}

// =====================================================================
// Kernel C: fused pair MLP, single-pass fp16 HMMA
// CTA: 128 pairs (8i x 16j) x N=256, K=512 in 8 chunks of 64.
// =====================================================================
__device__ __forceinline__ void prefetch_chunk(char* smem, int t, int buf, int tid,
                                               int bz, int i0, int j0) {
    // B chunk: 256 rows x 128B, SW128
    {
        char* base = smem + SM_B + buf * 32768;
#pragma unroll
        for (int u = 0; u < 8; ++u) {
            int s = u * 256 + tid;
            int n = s >> 3, g = s & 7;
            uint32_t dst = smem_u32(base) + sw128((uint32_t)(n * 128 + g * 16));
            CP16(dst, g_w2t + (size_t)n * HD + t * 64 + g * 8);
        }
    }
    // acs chunk: 8 a-rows + 16 c-rows, 64 floats each (row pitch 272B)
    char* acb = smem + SM_ACS + buf * 6528;
#pragma unroll
    for (int u = 0; u < 2; ++u) {
        int s = u * 256 + tid;
        if (s < 384) {
            int row = s >> 4, g = s & 15;
            const float* src = (row < 8)
                ? g_a + ((size_t)(bz * SQ + i0 + row)) * HD + t * 64 + g * 4
                : g_c + ((size_t)(bz * SQ + j0 + (row - 8))) * HD + t * 64 + g * 4;
            uint32_t dst = smem_u32(acb) + (uint32_t)(row * 272 + g * 16);
            CP16(dst, src);
        }
    }
    asm volatile("cp.async.commit_group;" ::: "memory");
}

__global__ __launch_bounds__(256, 1) void pair_hmma_kernel(
    const float* __restrict__ b1, const float* __restrict__ b2,
    const float* __restrict__ W3, const float* __restrict__ b3,
    float* __restrict__ out) {

    extern __shared__ char smem[];
    const int tid = threadIdx.x;
    const int wid = tid >> 5, lid = tid & 31;
    const int wm = wid >> 1, wn = wid & 1;
    const int bz = blockIdx.z;
    const int i0 = blockIdx.y * 8;
    const int j0 = blockIdx.x * 16;
    const uint32_t smb = smem_u32(smem);

    float* b1s = (float*)(smem + SM_B1);
    float* b2s = (float*)(smem + SM_B2);
    float* w3s = (float*)(smem + SM_W3);
    float* psm = (float*)(smem + SM_PSM);

    // stage biases
    if (tid < 128) ((float4*)b1s)[tid] = ((const float4*)b1)[tid];
    else if (tid < 192) ((float4*)b2s)[tid - 128] = ((const float4*)b2)[tid - 128];
    else ((float4*)w3s)[tid - 192] = ((const float4*)W3)[tid - 192];

    prefetch_chunk((char*)smem, 0, 0, tid, bz, i0, j0);

    float acc[2][16][4];
#pragma unroll
    for (int mf = 0; mf < 2; mf++)
#pragma unroll
        for (int nf = 0; nf < 16; nf++)
#pragma unroll
            for (int e = 0; e < 4; e++) acc[mf][nf][e] = 0.f;

    // ldmatrix per-lane constants
    const int rA = wm * 32 + (lid & 15);
    const uint32_t xorA = (uint32_t)((rA & 7) << 4);
    const int rB = wn * 128 + (lid & 15);
    const uint32_t xorB = (uint32_t)((rB & 7) << 4);
    const uint32_t khb = (uint32_t)((lid >> 4) << 4);

    // build-phase mapping: thread owns pair p, k-half kh (32 k values)
    const int p = tid & 127, kh = tid >> 7;
    const int iloc = p >> 4, jloc = p & 15;
    const uint32_t aXor = (uint32_t)((p & 7) << 4);

    for (int t = 0; t < 8; ++t) {
        const int cur = t & 1;
        asm volatile("cp.async.wait_group 0;" ::: "memory");
        __syncthreads();   // chunk t data visible; prev MMA done -> bufs free

        if (t + 1 < 8) prefetch_chunk((char*)smem, t + 1, cur ^ 1, tid, bz, i0, j0);

        // ---- build A(t): h1 = relu(a_i + c_j + b1) -> fp16 ----
        {
            const float* arow = (const float*)(smem + SM_ACS + cur * 6528 + iloc * 272);
            const float* crow = (const float*)(smem + SM_ACS + cur * 6528 + (8 + jloc) * 272);
            uint32_t hv[16];
#pragma unroll
            for (int q = 0; q < 8; ++q) {
                float4 av = *(const float4*)(arow + kh * 32 + q * 4);
                float4 cv = *(const float4*)(crow + kh * 32 + q * 4);
                float4 bb = *(const float4*)(b1s + t * 64 + kh * 32 + q * 4);
                float v0 = fmaxf(av.x + cv.x + bb.x, 0.f);
                float v1 = fmaxf(av.y + cv.y + bb.y, 0.f);
                float v2 = fmaxf(av.z + cv.z + bb.z, 0.f);
                float v3 = fmaxf(av.w + cv.w + bb.w, 0.f);
                hv[q * 2]     = cvt_f16x2(v0, v1);
                hv[q * 2 + 1] = cvt_f16x2(v2, v3);
            }
            char* ah = (char*)smem + SM_A + cur * 16384;
#pragma unroll
            for (int s = 0; s < 4; ++s) {
                uint32_t off = (uint32_t)(p * 128) + (((uint32_t)(kh * 64 + s * 16)) ^ aXor);
                *(uint4*)(ah + off) = make_uint4(hv[s*4], hv[s*4+1], hv[s*4+2], hv[s*4+3]);
            }
        }
        __syncthreads();   // A(t) visible

        // ---- mma over chunk t: Af * Bf ----
        const uint32_t Ah = smb + SM_A + cur * 16384;
        const uint32_t Bh = smb + SM_B + cur * 32768;
#pragma unroll
        for (int ks = 0; ks < 4; ++ks) {
            const uint32_t koff = ((uint32_t)(ks * 32) + khb);
            const uint32_t aoff = (uint32_t)(rA * 128) + (koff ^ xorA);
            uint32_t ah0[4], ah1[4];
            LDSM4(ah0, Ah + aoff);
            LDSM4(ah1, Ah + aoff + 16 * 128);
            const uint32_t bko = koff ^ xorB;
#pragma unroll
            for (int nfp = 0; nfp < 8; ++nfp) {
                uint32_t boff = (uint32_t)((rB + nfp * 16) * 128) + bko;
                uint32_t bh[4];
                LDSM4(bh, Bh + boff);
                MMA16816(acc[0][2 * nfp],     ah0, bh[0], bh[2]);
                MMA16816(acc[0][2 * nfp + 1], ah0, bh[1], bh[3]);
                MMA16816(acc[1][2 * nfp],     ah1, bh[0], bh[2]);
                MMA16816(acc[1][2 * nfp + 1], ah1, bh[1], bh[3]);
            }
        }
    }

    // ---- epilogue: relu(+b2) . W3, reduce, sigmoid ----
    float pr[2][2] = {{0.f, 0.f}, {0.f, 0.f}};
#pragma unroll
    for (int nf = 0; nf < 16; ++nf) {
        const int n = wn * 128 + nf * 8 + 2 * (lid & 3);
        const float b2x = b2s[n], b2y = b2s[n + 1];
        const float w3x = w3s[n], w3y = w3s[n + 1];
#pragma unroll
        for (int mf = 0; mf < 2; ++mf) {
            pr[mf][0] += fmaxf(acc[mf][nf][0] + b2x, 0.f) * w3x
                       + fmaxf(acc[mf][nf][1] + b2y, 0.f) * w3y;
            pr[mf][1] += fmaxf(acc[mf][nf][2] + b2x, 0.f) * w3x
                       + fmaxf(acc[mf][nf][3] + b2y, 0.f) * w3y;
        }
    }
#pragma unroll
    for (int mf = 0; mf < 2; ++mf)
#pragma unroll
        for (int h = 0; h < 2; ++h) {
            pr[mf][h] += __shfl_xor_sync(0xffffffffu, pr[mf][h], 1);
            pr[mf][h] += __shfl_xor_sync(0xffffffffu, pr[mf][h], 2);
        }
    if ((lid & 3) == 0) {
#pragma unroll
        for (int mf = 0; mf < 2; ++mf)
#pragma unroll
            for (int h = 0; h < 2; ++h) {
                int row = wm * 32 + mf * 16 + (lid >> 2) + h * 8;
                psm[row * 2 + wn] = pr[mf][h];
            }
    }
    __syncthreads();
    if (tid < 128) {
        const float b3v = __ldg(b3);
        float lg = psm[tid * 2] + psm[tid * 2 + 1] + b3v;
        const int i = i0 + (tid >> 4);
        const int j = j0 + (tid & 15);
        out[((size_t)bz * SQ + i) * SQ + j] = 1.f / (1.f + __expf(-lg));
    }
}

// =====================================================================
extern "C" void kernel_launch(void* const* d_in, const int* in_sizes, int n_in,
                              void* d_out, int out_size) {
    const float* f  = (const float*)d_in[0];
    const float* W1 = (const float*)d_in[1];
    const float* b1 = (const float*)d_in[2];
    const float* W2 = (const float*)d_in[3];
    const float* b2 = (const float*)d_in[4];
    const float* W3 = (const float*)d_in[5];
    const float* b3 = (const float*)d_in[6];
    float* out = (float*)d_out;

    cudaFuncSetAttribute(pair_hmma_kernel,
                         cudaFuncAttributeMaxDynamicSharedMemorySize, SMEM_TOTAL);

    gemm_ac_kernel<<<dim3(8, 16, 2), 256>>>(f, W1);
    w2prep_kernel<<<512, 256>>>(W2);
    pair_hmma_kernel<<<dim3(32, 64, 2), 256, SMEM_TOTAL>>>(b1, b2, W3, b3, out);
}